// round 4
// baseline (speedup 1.0000x reference)
#include <cuda_runtime.h>

#define NB 2048
#define NT 128
#define NS 256
#define NV 29
#define NE 32
#define NH 64
#define EP 17      // encoder row pitch in float4 (16 data + 1 pad)
#define G  2
#define THREADS 512

// SMEM f4: encs 2*256*17=8704 | xh 2*40=80 | cpart 256
// floats:  buf2 1024 | cb 128 | reds 16 | fcbs 32
#define SMEM_BYTES ((8704 + 80 + 256) * 16 + (1024 + 128 + 16 + 32) * 4)

__device__ __forceinline__ float2 ffma2(float2 a, float2 b, float2 c) {
    union U { float2 f; unsigned long long u; };
    U ua, ub, uc, d;
    ua.f = a; ub.f = b; uc.f = c;
    asm("fma.rn.f32x2 %0, %1, %2, %3;" : "=l"(d.u) : "l"(ua.u), "l"(ub.u), "l"(uc.u));
    return d.f;
}
__device__ __forceinline__ float fast_sigmoid(float x) {
    return __frcp_rn(1.f + __expf(-x));
}
__device__ __forceinline__ float fast_tanh(float x) {
    return fmaf(-2.f, __frcp_rn(__expf(2.f * x) + 1.f), 1.f);
}

__global__ __launch_bounds__(THREADS, 1) void decoder_kernel(
    const int* __restrict__ y, const float* __restrict__ h0,
    const float* __restrict__ c0, const float* __restrict__ enc,
    const float* __restrict__ emb, const float* __restrict__ Wih,
    const float* __restrict__ Whh, const float* __restrict__ bih,
    const float* __restrict__ bhh, const float* __restrict__ fcW,
    const float* __restrict__ fcb, float* __restrict__ out)
{
    const int tid  = threadIdx.x;
    const int lane = tid & 31;
    const int warp = tid >> 5;
    const int b0   = blockIdx.x * G;

    extern __shared__ float4 sm4[];
    float4* encs  = sm4;                        // [G][NS][EP]
    float4* xh4   = encs + G * NS * EP;         // [G][40]: emb 0..7 | h 8..23 | ctx 24..39
    float4* cpart = xh4 + G * 40;               // [16 warps][16]
    float*  buf2  = (float*)(cpart + 256);      // [2 halves][G][256]
    float*  cb    = buf2 + 1024;                // [G][64]
    float*  reds  = cb + G * NH;                // [16]
    float*  fcbs  = reds + 16;                  // [NV]
    float*  xh    = (float*)xh4;

    // ---- one-time staging ----
    for (int i = tid; i < G * NS * 16; i += THREADS) {
        const int gg = i >> 12, r = (i >> 4) & 255, k = i & 15;
        encs[(gg * NS + r) * EP + k] =
            ((const float4*)(enc + (size_t)(b0 + gg) * NS * NH))[r * 16 + k];
    }
    if (tid < NV) fcbs[tid] = fcb[tid];
    if (tid < G * NH) {
        const int gg = tid >> 6, j = tid & 63;
        xh[gg * 160 + 32 + j] = h0[(b0 + gg) * NH + j];
        cb[gg * 64 + j]       = c0[(b0 + gg) * NH + j];
    }
    // emb for t=0
    if (tid < 16) {
        const int gg = tid >> 3, k = tid & 7;
        const int yv = y[(b0 + gg) * NT];
        xh4[gg * 40 + k] = ((const float4*)emb)[yv * 8 + k];
    }

    // ---- gate weights -> regs. Rearranged columns: [Wih_emb(8) | Whh(16) | Wih_ctx(16)]
    // half0: cols 0..19 (emb + h[0..11]); half1: cols 20..39 (h[12..15] + ctx)
    const int row  = tid & 255;
    const int half = tid >> 8;
    float4 w[20];
    {
        const float4* wi4 = (const float4*)Wih + row * 24;
        const float4* wh4 = (const float4*)Whh + row * 16;
        if (half == 0) {
            #pragma unroll
            for (int j = 0; j < 8; j++)  w[j] = wi4[j];          // emb cols
            #pragma unroll
            for (int j = 0; j < 12; j++) w[8 + j] = wh4[j];      // h cols 0..11
        } else {
            #pragma unroll
            for (int j = 0; j < 4; j++)  w[j] = wh4[12 + j];     // h cols 12..15
            #pragma unroll
            for (int j = 0; j < 16; j++) w[4 + j] = wi4[8 + j];  // ctx cols
        }
    }
    const float bsum = (half == 0) ? (bih[row] + bhh[row]) : 0.f;

    // ---- fcW -> regs (fixed per-thread mapping for P7) ----
    const int s  = tid & 255;
    const int v  = s >> 3;
    const int l  = s & 7;
    const int g7 = tid >> 8;
    float4 fw0, fw1, fw2, fw3;
    if (v < NV) {
        const float4* fc4 = (const float4*)fcW + v * 32;
        fw0 = fc4[l]; fw1 = fc4[8 + l]; fw2 = fc4[16 + l]; fw3 = fc4[24 + l];
    } else {
        fw0 = fw1 = fw2 = fw3 = make_float4(0.f, 0.f, 0.f, 0.f);
    }
    __syncthreads();

    // fused-phase fixed addressing
    const int sg   = warp >> 3;          // score group of this warp
    const int srow = (warp & 7) * 32;    // first of 32 rows owned by this warp
    const float4* hvbase = xh4 + sg * 40 + 8;
    const float4* erow   = encs + (sg * NS + srow + lane) * EP;
    const int crow = lane & 16;
    const float4* ecbase = encs + (sg * NS + srow + crow) * EP + (lane & 15);

    for (int t = 0; t < NT; t++) {
        // ---- fused: scores -> exp -> warp sum -> warp context partial ----
        float2 a0 = make_float2(0.f, 0.f), a1 = make_float2(0.f, 0.f);
        #pragma unroll
        for (int k = 0; k < 16; k++) {
            const float4 e = erow[k], hv = hvbase[k];
            a0 = ffma2(make_float2(e.x, e.y), make_float2(hv.x, hv.y), a0);
            a1 = ffma2(make_float2(e.z, e.w), make_float2(hv.z, hv.w), a1);
        }
        const float p = __expf(a0.x + a0.y + a1.x + a1.y);
        float sum = p;
        #pragma unroll
        for (int o = 16; o; o >>= 1) sum += __shfl_xor_sync(~0u, sum, o);
        if (lane == 0) reds[warp] = sum;

        float2 cXY = make_float2(0.f, 0.f), cZW = make_float2(0.f, 0.f);
        #pragma unroll
        for (int i = 0; i < 16; i++) {
            const float pi = __shfl_sync(~0u, p, crow + i);
            const float4 e = ecbase[i * EP];
            cXY = ffma2(make_float2(e.x, e.y), make_float2(pi, pi), cXY);
            cZW = ffma2(make_float2(e.z, e.w), make_float2(pi, pi), cZW);
        }
        cXY.x += __shfl_xor_sync(~0u, cXY.x, 16);
        cXY.y += __shfl_xor_sync(~0u, cXY.y, 16);
        cZW.x += __shfl_xor_sync(~0u, cZW.x, 16);
        cZW.y += __shfl_xor_sync(~0u, cZW.y, 16);
        if (lane < 16)
            cpart[warp * 16 + lane] = make_float4(cXY.x, cXY.y, cZW.x, cZW.y);
        __syncthreads();  // B1

        // ---- W2: P4 (warp 15) || P5a (warps 0-7: emb+h gate partials) ----
        if (warp == 15) {
            const int gg = lane >> 4, k4 = lane & 15;
            float ssum = 0.f;
            #pragma unroll
            for (int i = 0; i < 8; i++) ssum += reds[gg * 8 + i];
            const float iv = __frcp_rn(ssum);
            float4 a = make_float4(0.f, 0.f, 0.f, 0.f);
            #pragma unroll
            for (int w8 = 0; w8 < 8; w8++) {
                const float4 vv = cpart[(gg * 8 + w8) * 16 + k4];
                a.x += vv.x; a.y += vv.y; a.z += vv.z; a.w += vv.w;
            }
            xh4[gg * 40 + 24 + k4] = make_float4(a.x * iv, a.y * iv, a.z * iv, a.w * iv);
        }
        if (half == 0) {
            const float4* x0 = xh4;        // g0 cols 0..19
            const float4* x1 = xh4 + 40;   // g1 cols 0..19
            float2 p0 = make_float2(0.f, 0.f), q0 = make_float2(0.f, 0.f);
            float2 p1 = make_float2(0.f, 0.f), q1 = make_float2(0.f, 0.f);
            #pragma unroll
            for (int j = 0; j < 20; j++) {
                const float4 wv = w[j];
                const float4 xa = x0[j];
                p0 = ffma2(make_float2(wv.x, wv.y), make_float2(xa.x, xa.y), p0);
                q0 = ffma2(make_float2(wv.z, wv.w), make_float2(xa.z, xa.w), q0);
                const float4 xb = x1[j];
                p1 = ffma2(make_float2(wv.x, wv.y), make_float2(xb.x, xb.y), p1);
                q1 = ffma2(make_float2(wv.z, wv.w), make_float2(xb.z, xb.w), q1);
            }
            buf2[row]       = p0.x + p0.y + q0.x + q0.y + bsum;
            buf2[256 + row] = p1.x + p1.y + q1.x + q1.y + bsum;
        }
        __syncthreads();  // B2

        // ---- W3: P5b (warps 8-15: h_hi+ctx) || emb prefetch for t+1 ----
        if (half == 1) {
            const float4* x0 = xh4 + 20;
            const float4* x1 = xh4 + 60;
            float2 p0 = make_float2(0.f, 0.f), q0 = make_float2(0.f, 0.f);
            float2 p1 = make_float2(0.f, 0.f), q1 = make_float2(0.f, 0.f);
            #pragma unroll
            for (int j = 0; j < 20; j++) {
                const float4 wv = w[j];
                const float4 xa = x0[j];
                p0 = ffma2(make_float2(wv.x, wv.y), make_float2(xa.x, xa.y), p0);
                q0 = ffma2(make_float2(wv.z, wv.w), make_float2(xa.z, xa.w), q0);
                const float4 xb = x1[j];
                p1 = ffma2(make_float2(wv.x, wv.y), make_float2(xb.x, xb.y), p1);
                q1 = ffma2(make_float2(wv.z, wv.w), make_float2(xb.z, xb.w), q1);
            }
            buf2[512 + row] = p0.x + p0.y + q0.x + q0.y;
            buf2[768 + row] = p1.x + p1.y + q1.x + q1.y;
        } else if (tid < 16 && t + 1 < NT) {
            const int gg = tid >> 3, k = tid & 7;
            const int yv = y[(b0 + gg) * NT + t + 1];
            xh4[gg * 40 + k] = ((const float4*)emb)[yv * 8 + k];
        }
        __syncthreads();  // B3

        // ---- W4: P6 LSTM elementwise (i,f,g,o) ----
        if (tid < G * NH) {
            const int gg = tid >> 6, j = tid & 63;
            const float* g0p = buf2 + gg * 256;
            const float* g1p = buf2 + 512 + gg * 256;
            const float ig = g0p[j]       + g1p[j];
            const float fg = g0p[64 + j]  + g1p[64 + j];
            const float gt = g0p[128 + j] + g1p[128 + j];
            const float og = g0p[192 + j] + g1p[192 + j];
            const float cn = fmaf(fast_sigmoid(fg), cb[gg * 64 + j],
                                  fast_sigmoid(ig) * fast_tanh(gt));
            cb[gg * 64 + j] = cn;
            xh[gg * 160 + 32 + j] = fast_sigmoid(og) * fast_tanh(cn);
        }
        __syncthreads();  // B4

        // ---- P7: logits, fcW from registers ----
        {
            float acc = 0.f;
            if (v < NV) {
                const float4 h0v = xh4[g7 * 40 + 8 + l];
                const float4 h1v = xh4[g7 * 40 + 16 + l];
                const float4 c0v = xh4[g7 * 40 + 24 + l];
                const float4 c1v = xh4[g7 * 40 + 32 + l];
                float2 a2 = make_float2(0.f, 0.f);
                a2 = ffma2(make_float2(fw0.x, fw0.y), make_float2(h0v.x, h0v.y), a2);
                a2 = ffma2(make_float2(fw0.z, fw0.w), make_float2(h0v.z, h0v.w), a2);
                a2 = ffma2(make_float2(fw1.x, fw1.y), make_float2(h1v.x, h1v.y), a2);
                a2 = ffma2(make_float2(fw1.z, fw1.w), make_float2(h1v.z, h1v.w), a2);
                a2 = ffma2(make_float2(fw2.x, fw2.y), make_float2(c0v.x, c0v.y), a2);
                a2 = ffma2(make_float2(fw2.z, fw2.w), make_float2(c0v.z, c0v.w), a2);
                a2 = ffma2(make_float2(fw3.x, fw3.y), make_float2(c1v.x, c1v.y), a2);
                a2 = ffma2(make_float2(fw3.z, fw3.w), make_float2(c1v.z, c1v.w), a2);
                acc = a2.x + a2.y;
            }
            acc += __shfl_down_sync(~0u, acc, 4, 8);
            acc += __shfl_down_sync(~0u, acc, 2, 8);
            acc += __shfl_down_sync(~0u, acc, 1, 8);
            if (v < NV && l == 0)
                out[((size_t)(b0 + g7) * NT + t) * NV + v] = acc + fcbs[v];
        }
        // next-iter writes are ordered behind B1/B2 of the next step
    }
}

extern "C" void kernel_launch(void* const* d_in, const int* in_sizes, int n_in,
                              void* d_out, int out_size) {
    const int*   y    = (const int*)  d_in[0];
    const float* h0   = (const float*)d_in[1];
    const float* c0   = (const float*)d_in[2];
    const float* enc  = (const float*)d_in[3];
    const float* emb  = (const float*)d_in[4];
    const float* Wih  = (const float*)d_in[5];
    const float* Whh  = (const float*)d_in[6];
    const float* bih  = (const float*)d_in[7];
    const float* bhh  = (const float*)d_in[8];
    const float* fcW  = (const float*)d_in[9];
    const float* fcb  = (const float*)d_in[10];
    float* out = (float*)d_out;

    cudaFuncSetAttribute(decoder_kernel,
                         cudaFuncAttributeMaxDynamicSharedMemorySize, SMEM_BYTES);
    decoder_kernel<<<NB / G, THREADS, SMEM_BYTES>>>(y, h0, c0, enc, emb, Wih, Whh,
                                                    bih, bhh, fcW, fcb, out);
}